// round 8
// baseline (speedup 1.0000x reference)
#include <cuda_runtime.h>
#include <math.h>

#define BATCH 512
#define INDIM 256
#define HIDD  512
#define HID2  256
#define PAT   10
#define NCTA  148

typedef unsigned long long u64;

// -------- scratch (no allocations allowed) --------
__device__ __align__(128) float g_H [BATCH * HIDD];
__device__ __align__(128) float g_H2[BATCH * HID2];
__device__ __align__(128) float g_A [BATCH * HIDD];
__device__ __align__(128) float g_C [BATCH * HIDD];

// -------- grid-wide barrier state (monotonic, replay-safe) --------
__device__ unsigned g_cnt = 0;
__device__ unsigned g_rel = 0;

__device__ __forceinline__ void grid_bar() {
    __syncthreads();
    if (threadIdx.x == 0) {
        __threadfence();
        const unsigned a = atomicAdd(&g_cnt, 1u) + 1u;          // 1-based arrival
        const unsigned target = ((a + NCTA - 1u) / NCTA) * NCTA; // my generation end
        if (a == target) {
            atomicMax(&g_rel, target);
        } else {
            volatile unsigned* vp = &g_rel;
            while (*vp < target) { __nanosleep(64); }
        }
        __threadfence();
    }
    __syncthreads();
}

// ---------- packed f32x2 helpers (sm_103a) ----------
__device__ __forceinline__ u64 pack2(float lo, float hi) {
    u64 r; asm("mov.b64 %0, {%1, %2};" : "=l"(r) : "f"(lo), "f"(hi)); return r;
}
__device__ __forceinline__ void unpack2(u64 v, float& lo, float& hi) {
    asm("mov.b64 {%0, %1}, %2;" : "=f"(lo), "=f"(hi) : "l"(v));
}
__device__ __forceinline__ u64 ffma2(u64 a, u64 b, u64 c) {
    u64 d; asm("fma.rn.f32x2 %0, %1, %2, %3;" : "=l"(d) : "l"(a), "l"(b), "l"(c)); return d;
}
__device__ __forceinline__ u64 dup2(float v) { return pack2(v, v); }

// ============================================================
// Split-K2 GEMM tile (R6-proven): 64m x 32n, 256 thr = 2 K-groups.
// mode 0: BN(+b1)+ReLU ; 1: none ; 2: +p0 ; 3: relu(+p0)
// ============================================================
__device__ __forceinline__ void gemm_sk2(
    const float* __restrict__ X, const float* __restrict__ W,
    float* __restrict__ Out, int N, int Kstr, int m0, int n0, int mode,
    const float* __restrict__ p0, const float* __restrict__ p1,
    const float* __restrict__ p2, const float* __restrict__ p3,
    const float* __restrict__ p4, float* sm, float* ex)
{
    const int tid = threadIdx.x;
    const int g   = tid >> 7;
    const int t   = tid & 127;

    float* Xs = sm + g * 3072;
    float* Wt = Xs + 2048;

    const int txn = t & 7;
    const int tym = t >> 3;

    const int xrow = t & 63;
    const int xkq  = t >> 6;
    const int wrow = t & 31;
    const int wkq  = t >> 5;

    const int kb = g * (Kstr >> 1);
    const float* Xg = X + (size_t)(m0 + xrow) * Kstr + kb;
    const float* Wg = W + (size_t)(n0 + wrow) * Kstr + kb;

    {
        float4 v0 = *(const float4*)(Xg + xkq * 4);
        float4 v1 = *(const float4*)(Xg + (xkq + 2) * 4);
        float4 wv = *(const float4*)(Wg + wkq * 4);
        Xs[(xkq*4+0)*64 + xrow] = v0.x; Xs[(xkq*4+1)*64 + xrow] = v0.y;
        Xs[(xkq*4+2)*64 + xrow] = v0.z; Xs[(xkq*4+3)*64 + xrow] = v0.w;
        Xs[((xkq+2)*4+0)*64 + xrow] = v1.x; Xs[((xkq+2)*4+1)*64 + xrow] = v1.y;
        Xs[((xkq+2)*4+2)*64 + xrow] = v1.z; Xs[((xkq+2)*4+3)*64 + xrow] = v1.w;
        Wt[(wkq*4+0)*32 + wrow] = wv.x; Wt[(wkq*4+1)*32 + wrow] = wv.y;
        Wt[(wkq*4+2)*32 + wrow] = wv.z; Wt[(wkq*4+3)*32 + wrow] = wv.w;
    }
    __syncthreads();

    u64 acc[4][2];
#pragma unroll
    for (int r = 0; r < 4; r++) { acc[r][0] = 0ull; acc[r][1] = 0ull; }

    const int NC = Kstr >> 5;
#pragma unroll 1
    for (int c = 0; c < NC; ++c) {
        const float* Xb = Xs + (c & 1) * 1024;
        const float* Wb = Wt + (c & 1) * 512;

        float4 v0, v1, wv;
        const bool pf = (c + 1 < NC);
        if (pf) {
            const int k0 = (c + 1) << 4;
            v0 = *(const float4*)(Xg + k0 + xkq * 4);
            v1 = *(const float4*)(Xg + k0 + (xkq + 2) * 4);
            wv = *(const float4*)(Wg + k0 + wkq * 4);
        }

#pragma unroll
        for (int kk = 0; kk < 16; kk++) {
            float4 a = *(const float4*)&Xb[kk * 64 + (tym << 2)];
            ulonglong2 b = *(const ulonglong2*)&Wb[kk * 32 + (txn << 2)];
            const u64 a0 = dup2(a.x), a1 = dup2(a.y);
            const u64 a2 = dup2(a.z), a3 = dup2(a.w);
            acc[0][0] = ffma2(a0, b.x, acc[0][0]); acc[0][1] = ffma2(a0, b.y, acc[0][1]);
            acc[1][0] = ffma2(a1, b.x, acc[1][0]); acc[1][1] = ffma2(a1, b.y, acc[1][1]);
            acc[2][0] = ffma2(a2, b.x, acc[2][0]); acc[2][1] = ffma2(a2, b.y, acc[2][1]);
            acc[3][0] = ffma2(a3, b.x, acc[3][0]); acc[3][1] = ffma2(a3, b.y, acc[3][1]);
        }

        if (pf) {
            float* Xn = Xs + ((c + 1) & 1) * 1024;
            float* Wn = Wt + ((c + 1) & 1) * 512;
            Xn[(xkq*4+0)*64 + xrow] = v0.x; Xn[(xkq*4+1)*64 + xrow] = v0.y;
            Xn[(xkq*4+2)*64 + xrow] = v0.z; Xn[(xkq*4+3)*64 + xrow] = v0.w;
            Xn[((xkq+2)*4+0)*64 + xrow] = v1.x; Xn[((xkq+2)*4+1)*64 + xrow] = v1.y;
            Xn[((xkq+2)*4+2)*64 + xrow] = v1.z; Xn[((xkq+2)*4+3)*64 + xrow] = v1.w;
            Wn[(wkq*4+0)*32 + wrow] = wv.x; Wn[(wkq*4+1)*32 + wrow] = wv.y;
            Wn[(wkq*4+2)*32 + wrow] = wv.z; Wn[(wkq*4+3)*32 + wrow] = wv.w;
        }
        __syncthreads();
    }

    // ---- combine (no early return: persistent-loop safe) ----
    if (g == 1) {
#pragma unroll
        for (int r = 0; r < 4; r++) {
            float v0, v1, v2, v3;
            unpack2(acc[r][0], v0, v1);
            unpack2(acc[r][1], v2, v3);
            *(float4*)&ex[(tym * 4 + r) * 32 + txn * 4] = make_float4(v0, v1, v2, v3);
        }
    }
    __syncthreads();
    if (g == 0) {
        float va[4][4];
#pragma unroll
        for (int r = 0; r < 4; r++) {
            unpack2(acc[r][0], va[r][0], va[r][1]);
            unpack2(acc[r][1], va[r][2], va[r][3]);
            float4 e = *(const float4*)&ex[(tym * 4 + r) * 32 + txn * 4];
            va[r][0] += e.x; va[r][1] += e.y; va[r][2] += e.z; va[r][3] += e.w;
        }

        const int n = n0 + txn * 4;
        float4 q0 = make_float4(0.f,0.f,0.f,0.f), q1 = q0, q2 = q0, q3 = q0, q4 = q0;
        if (mode == 0) {
            q0 = *(const float4*)(p0 + n); q1 = *(const float4*)(p1 + n);
            q2 = *(const float4*)(p2 + n); q3 = *(const float4*)(p3 + n);
            q4 = *(const float4*)(p4 + n);
        } else if (mode == 2 || mode == 3) {
            q0 = *(const float4*)(p0 + n);
        }
        const float* bias = &q0.x;
        const float* gam  = &q1.x;
        const float* bet  = &q2.x;
        const float* mean = &q3.x;
        const float* var  = &q4.x;

#pragma unroll
        for (int r = 0; r < 4; r++) {
            float v[4];
#pragma unroll
            for (int c2 = 0; c2 < 4; c2++) {
                float v2 = va[r][c2];
                if (mode == 0) {
                    v2 += bias[c2];
                    v2 = gam[c2] * (v2 - mean[c2]) * rsqrtf(var[c2] + 1e-5f) + bet[c2];
                    v2 = fmaxf(v2, 0.f);
                } else if (mode == 2) {
                    v2 += bias[c2];
                } else if (mode == 3) {
                    v2 = fmaxf(v2 + bias[c2], 0.f);
                }
                v[c2] = v2;
            }
            *(float4*)(Out + (size_t)(m0 + tym * 4 + r) * N + n) =
                make_float4(v[0], v[1], v[2], v[3]);
        }
    }
}

// ============================================================
// Similarity tile job (R6-proven): 32x32 pair tile, 256 thr,
// split-K2, 2i x 4j micro.
// ============================================================
__device__ __forceinline__ void sim_job(
    int jb, const float* __restrict__ ws2, const float* __restrict__ bs2p,
    float* __restrict__ out_sim, float* sm)
{
    const int tid = threadIdx.x;
    const int g   = tid >> 7;
    const int t   = tid & 127;

    float* As = sm + g * 4160;
    float* Cs = As + 2048;
    float* Ws = As + 4096;
    float* ex = sm + 8320;

    int rb = jb, bi = 0;
    while (rb >= 16 - bi) { rb -= 16 - bi; ++bi; }
    const int bj = bi + rb;
    const int i0 = bi * 32, j0 = bj * 32;

    const int tx = t & 7;
    const int ty = t >> 3;

    const int lrow = t & 31;
    const int lkq  = t >> 5;
    const int kb   = g * 256;

    const float* Ag = g_A + (size_t)(i0 + lrow) * HIDD + kb;
    const float* Cg = g_C + (size_t)(j0 + lrow) * HIDD + kb;
    const float* Wg = ws2 + kb;

    {
        float4 a0 = *(const float4*)(Ag + lkq * 4);
        float4 a1 = *(const float4*)(Ag + (lkq + 4) * 4);
        float4 c0 = *(const float4*)(Cg + lkq * 4);
        float4 c1 = *(const float4*)(Cg + (lkq + 4) * 4);
        As[(lkq*4+0)*32 + lrow] = a0.x; As[(lkq*4+1)*32 + lrow] = a0.y;
        As[(lkq*4+2)*32 + lrow] = a0.z; As[(lkq*4+3)*32 + lrow] = a0.w;
        As[((lkq+4)*4+0)*32 + lrow] = a1.x; As[((lkq+4)*4+1)*32 + lrow] = a1.y;
        As[((lkq+4)*4+2)*32 + lrow] = a1.z; As[((lkq+4)*4+3)*32 + lrow] = a1.w;
        Cs[(lkq*4+0)*32 + lrow] = c0.x; Cs[(lkq*4+1)*32 + lrow] = c0.y;
        Cs[(lkq*4+2)*32 + lrow] = c0.z; Cs[(lkq*4+3)*32 + lrow] = c0.w;
        Cs[((lkq+4)*4+0)*32 + lrow] = c1.x; Cs[((lkq+4)*4+1)*32 + lrow] = c1.y;
        Cs[((lkq+4)*4+2)*32 + lrow] = c1.z; Cs[((lkq+4)*4+3)*32 + lrow] = c1.w;
        if (t < 8) *(float4*)&Ws[t * 4] = *(const float4*)(Wg + t * 4);
    }
    __syncthreads();

    float acc[2][4];
#pragma unroll
    for (int r = 0; r < 2; r++)
#pragma unroll
        for (int c = 0; c < 4; c++) acc[r][c] = 0.f;

#pragma unroll 1
    for (int ch = 0; ch < 8; ++ch) {
        const float* Ab = As + (ch & 1) * 1024;
        const float* Cb = Cs + (ch & 1) * 1024;
        const float* Wb = Ws + (ch & 1) * 32;

        float4 a0, a1, c0, c1, wv;
        const bool pf = (ch + 1 < 8);
        if (pf) {
            const int k0 = (ch + 1) << 5;
            a0 = *(const float4*)(Ag + k0 + lkq * 4);
            a1 = *(const float4*)(Ag + k0 + (lkq + 4) * 4);
            c0 = *(const float4*)(Cg + k0 + lkq * 4);
            c1 = *(const float4*)(Cg + k0 + (lkq + 4) * 4);
            if (t < 8) wv = *(const float4*)(Wg + k0 + t * 4);
        }

#pragma unroll
        for (int kk = 0; kk < 32; kk++) {
            float2 a  = *(const float2*)&Ab[kk * 32 + ty * 2];
            float4 cc = *(const float4*)&Cb[kk * 32 + tx * 4];
            const float w = Wb[kk];
            acc[0][0] += fmaxf(a.x + cc.x, 0.f) * w;
            acc[0][1] += fmaxf(a.x + cc.y, 0.f) * w;
            acc[0][2] += fmaxf(a.x + cc.z, 0.f) * w;
            acc[0][3] += fmaxf(a.x + cc.w, 0.f) * w;
            acc[1][0] += fmaxf(a.y + cc.x, 0.f) * w;
            acc[1][1] += fmaxf(a.y + cc.y, 0.f) * w;
            acc[1][2] += fmaxf(a.y + cc.z, 0.f) * w;
            acc[1][3] += fmaxf(a.y + cc.w, 0.f) * w;
        }

        if (pf) {
            float* An = As + ((ch + 1) & 1) * 1024;
            float* Cn = Cs + ((ch + 1) & 1) * 1024;
            An[(lkq*4+0)*32 + lrow] = a0.x; An[(lkq*4+1)*32 + lrow] = a0.y;
            An[(lkq*4+2)*32 + lrow] = a0.z; An[(lkq*4+3)*32 + lrow] = a0.w;
            An[((lkq+4)*4+0)*32 + lrow] = a1.x; An[((lkq+4)*4+1)*32 + lrow] = a1.y;
            An[((lkq+4)*4+2)*32 + lrow] = a1.z; An[((lkq+4)*4+3)*32 + lrow] = a1.w;
            Cn[(lkq*4+0)*32 + lrow] = c0.x; Cn[(lkq*4+1)*32 + lrow] = c0.y;
            Cn[(lkq*4+2)*32 + lrow] = c0.z; Cn[(lkq*4+3)*32 + lrow] = c0.w;
            Cn[((lkq+4)*4+0)*32 + lrow] = c1.x; Cn[((lkq+4)*4+1)*32 + lrow] = c1.y;
            Cn[((lkq+4)*4+2)*32 + lrow] = c1.z; Cn[((lkq+4)*4+3)*32 + lrow] = c1.w;
            if (t < 8) *(float4*)&Ws[((ch + 1) & 1) * 32 + t * 4] = wv;
        }
        __syncthreads();
    }

    if (g == 1) {
        *(float4*)&ex[t * 8]     = make_float4(acc[0][0], acc[0][1], acc[0][2], acc[0][3]);
        *(float4*)&ex[t * 8 + 4] = make_float4(acc[1][0], acc[1][1], acc[1][2], acc[1][3]);
    }
    __syncthreads();
    if (g == 0) {
        float4 e0 = *(const float4*)&ex[t * 8];
        float4 e1 = *(const float4*)&ex[t * 8 + 4];
        acc[0][0] += e0.x; acc[0][1] += e0.y; acc[0][2] += e0.z; acc[0][3] += e0.w;
        acc[1][0] += e1.x; acc[1][1] += e1.y; acc[1][2] += e1.z; acc[1][3] += e1.w;

        const float bs2 = *bs2p;
#pragma unroll
        for (int r = 0; r < 2; r++) {
#pragma unroll
            for (int c = 0; c < 4; c++) {
                const int i = i0 + ty * 2 + r;
                const int j = j0 + tx * 4 + c;
                if (i < j) {
                    const float s = 1.f / (1.f + __expf(-(acc[r][c] + bs2)));
                    out_sim[(size_t)i * BATCH + j] = s;
                    out_sim[(size_t)j * BATCH + i] = s;
                } else if (i == j) {
                    out_sim[(size_t)i * BATCH + j] = 0.f;
                }
            }
        }
    }
}

// ============================================================
// Scores job: 8 rows per job (one warp each), 256 thr.
// ============================================================
__device__ __forceinline__ void scores_job(
    int jb, const float* __restrict__ W3, const float* __restrict__ b3,
    float* __restrict__ out_probs, float* __restrict__ out_scores)
{
    const int warp = threadIdx.x >> 5;
    const int lane = threadIdx.x & 31;
    const int row  = jb * 8 + warp;
    const float* h = g_H2 + (size_t)row * HID2;

    float acc[PAT];
#pragma unroll
    for (int p = 0; p < PAT; p++) acc[p] = 0.f;

    for (int k = lane; k < HID2; k += 32) {
        const float hv = h[k];
#pragma unroll
        for (int p = 0; p < PAT; p++) acc[p] += hv * W3[p * HID2 + k];
    }
#pragma unroll
    for (int p = 0; p < PAT; p++) {
#pragma unroll
        for (int off = 16; off; off >>= 1)
            acc[p] += __shfl_xor_sync(0xFFFFFFFFu, acc[p], off);
    }
    if (lane == 0) {
        float s[PAT], e[PAT];
        float mx = -1e30f;
#pragma unroll
        for (int p = 0; p < PAT; p++) { s[p] = acc[p] + b3[p]; mx = fmaxf(mx, s[p]); }
        float sum = 0.f;
#pragma unroll
        for (int p = 0; p < PAT; p++) { e[p] = __expf(s[p] - mx); sum += e[p]; }
        const float inv = 1.f / sum;
#pragma unroll
        for (int p = 0; p < PAT; p++) {
            out_scores[row * PAT + p] = s[p];
            out_probs [row * PAT + p] = e[p] * inv;
        }
    }
}

// ============================================================
// Persistent mega-kernel: 148 CTAs x 256 threads, 3 phases.
// ============================================================
__global__ __launch_bounds__(256)
void k_all(const float* __restrict__ x,
           const float* __restrict__ W1, const float* __restrict__ b1,
           const float* __restrict__ gam, const float* __restrict__ bet,
           const float* __restrict__ mean, const float* __restrict__ var,
           const float* __restrict__ W2, const float* __restrict__ b2,
           const float* __restrict__ W3, const float* __restrict__ b3,
           const float* __restrict__ Wa, const float* __restrict__ Wb,
           const float* __restrict__ bs1, const float* __restrict__ ws2,
           const float* __restrict__ bs2,
           float* __restrict__ out_probs, float* __restrict__ out_scores,
           float* __restrict__ out_sim)
{
    __shared__ __align__(16) float sm[9344];
    float* ex_g = sm + 6144;

    // ---- Phase 1: projections H, A, C (384 tile jobs) ----
    for (int j = blockIdx.x; j < 384; j += NCTA) {
        const int z  = j / 128;
        const int r  = j % 128;
        const int m0 = (r >> 4) * 64;
        const int n0 = (r & 15) * 32;
        if (z == 0)
            gemm_sk2(x, W1, g_H, HIDD, INDIM, m0, n0, 0, b1, gam, bet, mean, var, sm, ex_g);
        else if (z == 1)
            gemm_sk2(x, Wa, g_A, HIDD, INDIM, m0, n0, 1,
                     (const float*)0, (const float*)0, (const float*)0,
                     (const float*)0, (const float*)0, sm, ex_g);
        else
            gemm_sk2(x, Wb, g_C, HIDD, INDIM, m0, n0, 2,
                     bs1, (const float*)0, (const float*)0,
                     (const float*)0, (const float*)0, sm, ex_g);
        __syncthreads();
    }
    grid_bar();

    // ---- Phase 2: similarity (136) + H2 (64) jobs ----
    for (int j = blockIdx.x; j < 200; j += NCTA) {
        if (j < 136) {
            sim_job(j, ws2, bs2, out_sim, sm);
        } else {
            const int idx = j - 136;
            gemm_sk2(g_H, W2, g_H2, HID2, HIDD, (idx >> 3) * 64, (idx & 7) * 32, 3,
                     b2, (const float*)0, (const float*)0,
                     (const float*)0, (const float*)0, sm, ex_g);
        }
        __syncthreads();
    }
    grid_bar();

    // ---- Phase 3: scores + softmax (64 jobs x 8 rows) ----
    for (int j = blockIdx.x; j < 64; j += NCTA)
        scores_job(j, W3, b3, out_probs, out_scores);
}

// ============================================================
extern "C" void kernel_launch(void* const* d_in, const int* in_sizes, int n_in,
                              void* d_out, int out_size)
{
    const float* x    = (const float*)d_in[0];
    const float* W1   = (const float*)d_in[1];
    const float* b1   = (const float*)d_in[2];
    const float* gam  = (const float*)d_in[3];
    const float* bet  = (const float*)d_in[4];
    const float* mean = (const float*)d_in[5];
    const float* var  = (const float*)d_in[6];
    const float* W2   = (const float*)d_in[7];
    const float* b2   = (const float*)d_in[8];
    const float* W3   = (const float*)d_in[9];
    const float* b3   = (const float*)d_in[10];
    const float* Wa   = (const float*)d_in[11];
    const float* Wb   = (const float*)d_in[12];
    const float* bs1  = (const float*)d_in[13];
    const float* ws2  = (const float*)d_in[14];
    const float* bs2  = (const float*)d_in[15];

    float* out        = (float*)d_out;
    float* out_probs  = out;
    float* out_scores = out + BATCH * PAT;
    float* out_sim    = out + 2 * BATCH * PAT;

    k_all<<<NCTA, 256>>>(x, W1, b1, gam, bet, mean, var, W2, b2, W3, b3,
                         Wa, Wb, bs1, ws2, bs2,
                         out_probs, out_scores, out_sim);
}

// round 9
// speedup vs baseline: 1.0979x; 1.0979x over previous
#include <cuda_runtime.h>
#include <math.h>

#define BATCH 512
#define INDIM 256
#define HIDD  512
#define HID2  256
#define PAT   10

typedef unsigned long long u64;

// -------- scratch (no allocations allowed) --------
__device__ __align__(128) float g_H [BATCH * HIDD];
__device__ __align__(128) float g_H2[BATCH * HID2];
__device__ __align__(128) float g_A [BATCH * HIDD];
__device__ __align__(128) float g_C [BATCH * HIDD];

// ---------- packed f32x2 helpers (sm_103a) ----------
__device__ __forceinline__ u64 pack2(float lo, float hi) {
    u64 r; asm("mov.b64 %0, {%1, %2};" : "=l"(r) : "f"(lo), "f"(hi)); return r;
}
__device__ __forceinline__ void unpack2(u64 v, float& lo, float& hi) {
    asm("mov.b64 {%0, %1}, %2;" : "=f"(lo), "=f"(hi) : "l"(v));
}
__device__ __forceinline__ u64 ffma2(u64 a, u64 b, u64 c) {
    u64 d; asm("fma.rn.f32x2 %0, %1, %2, %3;" : "=l"(d) : "l"(a), "l"(b), "l"(c)); return d;
}
__device__ __forceinline__ u64 dup2(float v) { return pack2(v, v); }

// Fused packed sim step: acc += relu(a2 + c2) * w2   (2 outputs)
// One asm block so ptxas can pair registers and kill the virtual movs.
__device__ __forceinline__ void step2(u64& acc, u64 a2, u64 c2, u64 w2) {
    asm("{\n\t"
        ".reg .f32 lo, hi;\n\t"
        ".reg .b64 s;\n\t"
        "add.rn.f32x2 s, %1, %2;\n\t"
        "mov.b64 {lo, hi}, s;\n\t"
        "max.f32 lo, lo, 0f00000000;\n\t"
        "max.f32 hi, hi, 0f00000000;\n\t"
        "mov.b64 s, {lo, hi};\n\t"
        "fma.rn.f32x2 %0, s, %3, %0;\n\t"
        "}"
        : "+l"(acc) : "l"(a2), "l"(c2), "l"(w2));
}

// ============================================================
// Split-K(2) GEMM tile (59.9us-proven): 64m x 32n, 256 thr =
// 2 independent 128-thr K-groups, 4x4 microtile, f32x2 FMA,
// double-buffered smem, one end-of-loop combine.
// mode 0: BN(+b1)+ReLU ; 1: none ; 2: +p0 ; 3: relu(+p0)
// ============================================================
__device__ __forceinline__ void gemm_sk2(
    const float* __restrict__ X, const float* __restrict__ W,
    float* __restrict__ Out, int N, int Kstr, int m0, int n0, int mode,
    const float* __restrict__ p0, const float* __restrict__ p1,
    const float* __restrict__ p2, const float* __restrict__ p3,
    const float* __restrict__ p4, float* sm, float* ex)
{
    const int tid = threadIdx.x;
    const int g   = tid >> 7;      // K-group 0/1
    const int t   = tid & 127;

    float* Xs = sm + g * 3072;    // 2 * 16 * 64
    float* Wt = Xs + 2048;        // 2 * 16 * 32

    const int txn = t & 7;        // n quad (4 cols)
    const int tym = t >> 3;       // m quad (4 rows), 0..15

    const int xrow = t & 63;      // X loader row
    const int xkq  = t >> 6;      // 0..1 (handles kq and kq+2)
    const int wrow = t & 31;      // W loader row
    const int wkq  = t >> 5;      // 0..3

    const int kb = g * (Kstr >> 1);
    const float* Xg = X + (size_t)(m0 + xrow) * Kstr + kb;
    const float* Wg = W + (size_t)(n0 + wrow) * Kstr + kb;

    // ---- load chunk 0 ----
    {
        float4 v0 = *(const float4*)(Xg + xkq * 4);
        float4 v1 = *(const float4*)(Xg + (xkq + 2) * 4);
        float4 wv = *(const float4*)(Wg + wkq * 4);
        Xs[(xkq*4+0)*64 + xrow] = v0.x; Xs[(xkq*4+1)*64 + xrow] = v0.y;
        Xs[(xkq*4+2)*64 + xrow] = v0.z; Xs[(xkq*4+3)*64 + xrow] = v0.w;
        Xs[((xkq+2)*4+0)*64 + xrow] = v1.x; Xs[((xkq+2)*4+1)*64 + xrow] = v1.y;
        Xs[((xkq+2)*4+2)*64 + xrow] = v1.z; Xs[((xkq+2)*4+3)*64 + xrow] = v1.w;
        Wt[(wkq*4+0)*32 + wrow] = wv.x; Wt[(wkq*4+1)*32 + wrow] = wv.y;
        Wt[(wkq*4+2)*32 + wrow] = wv.z; Wt[(wkq*4+3)*32 + wrow] = wv.w;
    }
    __syncthreads();

    u64 acc[4][2];
#pragma unroll
    for (int r = 0; r < 4; r++) { acc[r][0] = 0ull; acc[r][1] = 0ull; }

    const int NC = Kstr >> 5;     // chunks of 16 over K/2
#pragma unroll 1
    for (int c = 0; c < NC; ++c) {
        const float* Xb = Xs + (c & 1) * 1024;
        const float* Wb = Wt + (c & 1) * 512;

        float4 v0, v1, wv;
        const bool pf = (c + 1 < NC);
        if (pf) {
            const int k0 = (c + 1) << 4;
            v0 = *(const float4*)(Xg + k0 + xkq * 4);
            v1 = *(const float4*)(Xg + k0 + (xkq + 2) * 4);
            wv = *(const float4*)(Wg + k0 + wkq * 4);
        }

#pragma unroll
        for (int kk = 0; kk < 16; kk++) {
            float4 a = *(const float4*)&Xb[kk * 64 + (tym << 2)];
            ulonglong2 b = *(const ulonglong2*)&Wb[kk * 32 + (txn << 2)];
            const u64 a0 = dup2(a.x), a1 = dup2(a.y);
            const u64 a2 = dup2(a.z), a3 = dup2(a.w);
            acc[0][0] = ffma2(a0, b.x, acc[0][0]); acc[0][1] = ffma2(a0, b.y, acc[0][1]);
            acc[1][0] = ffma2(a1, b.x, acc[1][0]); acc[1][1] = ffma2(a1, b.y, acc[1][1]);
            acc[2][0] = ffma2(a2, b.x, acc[2][0]); acc[2][1] = ffma2(a2, b.y, acc[2][1]);
            acc[3][0] = ffma2(a3, b.x, acc[3][0]); acc[3][1] = ffma2(a3, b.y, acc[3][1]);
        }

        if (pf) {
            float* Xn = Xs + ((c + 1) & 1) * 1024;
            float* Wn = Wt + ((c + 1) & 1) * 512;
            Xn[(xkq*4+0)*64 + xrow] = v0.x; Xn[(xkq*4+1)*64 + xrow] = v0.y;
            Xn[(xkq*4+2)*64 + xrow] = v0.z; Xn[(xkq*4+3)*64 + xrow] = v0.w;
            Xn[((xkq+2)*4+0)*64 + xrow] = v1.x; Xn[((xkq+2)*4+1)*64 + xrow] = v1.y;
            Xn[((xkq+2)*4+2)*64 + xrow] = v1.z; Xn[((xkq+2)*4+3)*64 + xrow] = v1.w;
            Wn[(wkq*4+0)*32 + wrow] = wv.x; Wn[(wkq*4+1)*32 + wrow] = wv.y;
            Wn[(wkq*4+2)*32 + wrow] = wv.z; Wn[(wkq*4+3)*32 + wrow] = wv.w;
        }
        __syncthreads();
    }

    // ---- unpack partials ----
    float va[4][4];
#pragma unroll
    for (int r = 0; r < 4; r++) {
        unpack2(acc[r][0], va[r][0], va[r][1]);
        unpack2(acc[r][1], va[r][2], va[r][3]);
    }

    // ---- single combine: group1 -> ex, group0 adds ----
    if (g == 1) {
#pragma unroll
        for (int r = 0; r < 4; r++)
            *(float4*)&ex[(tym * 4 + r) * 32 + txn * 4] =
                make_float4(va[r][0], va[r][1], va[r][2], va[r][3]);
    }
    __syncthreads();
    if (g == 1) return;

#pragma unroll
    for (int r = 0; r < 4; r++) {
        float4 e = *(const float4*)&ex[(tym * 4 + r) * 32 + txn * 4];
        va[r][0] += e.x; va[r][1] += e.y; va[r][2] += e.z; va[r][3] += e.w;
    }

    // ---- epilogue ----
    const int n = n0 + txn * 4;
    float4 q0 = make_float4(0.f, 0.f, 0.f, 0.f), q1 = q0, q2 = q0, q3 = q0, q4 = q0;
    if (mode == 0) {
        q0 = *(const float4*)(p0 + n); q1 = *(const float4*)(p1 + n);
        q2 = *(const float4*)(p2 + n); q3 = *(const float4*)(p3 + n);
        q4 = *(const float4*)(p4 + n);
    } else if (mode == 2 || mode == 3) {
        q0 = *(const float4*)(p0 + n);
    }
    const float* bias = &q0.x;
    const float* gam  = &q1.x;
    const float* bet  = &q2.x;
    const float* mean = &q3.x;
    const float* var  = &q4.x;

#pragma unroll
    for (int r = 0; r < 4; r++) {
        float v[4];
#pragma unroll
        for (int c2 = 0; c2 < 4; c2++) {
            float v2 = va[r][c2];
            if (mode == 0) {
                v2 += bias[c2];
                v2 = gam[c2] * (v2 - mean[c2]) * rsqrtf(var[c2] + 1e-5f) + bet[c2];
                v2 = fmaxf(v2, 0.f);
            } else if (mode == 2) {
                v2 += bias[c2];
            } else if (mode == 3) {
                v2 = fmaxf(v2 + bias[c2], 0.f);
            }
            v[c2] = v2;
        }
        *(float4*)(Out + (size_t)(m0 + tym * 4 + r) * N + n) =
            make_float4(v[0], v[1], v[2], v[3]);
    }
}

// ============================================================
// Launch 1: three x-projections (H via BN+ReLU, A, C+bs1)
// grid (16 n-tiles, 8 m-tiles, 3 weights), 256 threads (split-K2).
// ============================================================
__global__ __launch_bounds__(256)
void k_proj(const float* __restrict__ x,
            const float* __restrict__ W1, const float* __restrict__ b1,
            const float* __restrict__ gam, const float* __restrict__ bet,
            const float* __restrict__ mean, const float* __restrict__ var,
            const float* __restrict__ Wa, const float* __restrict__ Wb,
            const float* __restrict__ bs1)
{
    __shared__ __align__(16) float sm[8192];   // 2*3072 bufs + 2048 ex
    float* ex = sm + 6144;
    const int m0 = blockIdx.y * 64;
    const int n0 = blockIdx.x * 32;
    const int z  = blockIdx.z;
    if (z == 0)
        gemm_sk2(x, W1, g_H, HIDD, INDIM, m0, n0, 0, b1, gam, bet, mean, var, sm, ex);
    else if (z == 1)
        gemm_sk2(x, Wa, g_A, HIDD, INDIM, m0, n0, 1,
                 nullptr, nullptr, nullptr, nullptr, nullptr, sm, ex);
    else
        gemm_sk2(x, Wb, g_C, HIDD, INDIM, m0, n0, 2,
                 bs1, nullptr, nullptr, nullptr, nullptr, sm, ex);
}

// ============================================================
// Launch 2: blocks [0,136) = similarity tiles (upper triangle),
//           blocks [136,200) = H2 = relu(H @ W2^T + b2) 64x32 tiles.
// 256 threads; both paths use 2-group split-K with one combine.
// sim: 32x32 pair tile, 2i x 4j micro (j packed into f32x2),
// per group K=256 in 8 chunks of 32, double-buffered.
// ============================================================
__global__ __launch_bounds__(256)
void k_simh2(const float* __restrict__ W2, const float* __restrict__ b2,
             const float* __restrict__ ws2, const float* __restrict__ bs2p,
             float* __restrict__ out_sim)
{
    __shared__ __align__(16) float sm[9344];

    if (blockIdx.x >= 136) {
        const int idx = blockIdx.x - 136;          // 0..63
        const int m0 = (idx >> 3) * 64;            // 8 m-tiles
        const int n0 = (idx & 7) * 32;             // 8 n-tiles
        gemm_sk2(g_H, W2, g_H2, HID2, HIDD, m0, n0, 3,
                 b2, nullptr, nullptr, nullptr, nullptr, sm, sm + 6144);
        return;
    }

    // ---- similarity tile ----
    const int tid = threadIdx.x;
    const int g   = tid >> 7;
    const int t   = tid & 127;

    float* As = sm + g * 4160;   // 2 * 32 * 32
    float* Cs = As + 2048;       // 2 * 32 * 32
    float* Ws = As + 4096;       // 2 * 32
    float* ex = sm + 8320;       // 1024 floats

    // decode upper-triangle tile (bi <= bj)
    int rb = blockIdx.x, bi = 0;
    while (rb >= 16 - bi) { rb -= 16 - bi; ++bi; }
    const int bj = bi + rb;
    const int i0 = bi * 32, j0 = bj * 32;

    const int tx = t & 7;     // j quad
    const int ty = t >> 3;    // i pair

    const int lrow = t & 31;
    const int lkq  = t >> 5;  // 0..3 (handles kq and kq+4)
    const int kb   = g * 256;

    const float* Ag = g_A + (size_t)(i0 + lrow) * HIDD + kb;
    const float* Cg = g_C + (size_t)(j0 + lrow) * HIDD + kb;
    const float* Wg = ws2 + kb;

    // ---- load chunk 0 ----
    {
        float4 a0 = *(const float4*)(Ag + lkq * 4);
        float4 a1 = *(const float4*)(Ag + (lkq + 4) * 4);
        float4 c0 = *(const float4*)(Cg + lkq * 4);
        float4 c1 = *(const float4*)(Cg + (lkq + 4) * 4);
        As[(lkq*4+0)*32 + lrow] = a0.x; As[(lkq*4+1)*32 + lrow] = a0.y;
        As[(lkq*4+2)*32 + lrow] = a0.z; As[(lkq*4+3)*32 + lrow] = a0.w;
        As[((lkq+4)*4+0)*32 + lrow] = a1.x; As[((lkq+4)*4+1)*32 + lrow] = a1.y;
        As[((lkq+4)*4+2)*32 + lrow] = a1.z; As[((lkq+4)*4+3)*32 + lrow] = a1.w;
        Cs[(lkq*4+0)*32 + lrow] = c0.x; Cs[(lkq*4+1)*32 + lrow] = c0.y;
        Cs[(lkq*4+2)*32 + lrow] = c0.z; Cs[(lkq*4+3)*32 + lrow] = c0.w;
        Cs[((lkq+4)*4+0)*32 + lrow] = c1.x; Cs[((lkq+4)*4+1)*32 + lrow] = c1.y;
        Cs[((lkq+4)*4+2)*32 + lrow] = c1.z; Cs[((lkq+4)*4+3)*32 + lrow] = c1.w;
        if (t < 8) *(float4*)&Ws[t * 4] = *(const float4*)(Wg + t * 4);
    }
    __syncthreads();

    u64 acc2[2][2];
    acc2[0][0] = 0ull; acc2[0][1] = 0ull;
    acc2[1][0] = 0ull; acc2[1][1] = 0ull;

#pragma unroll 1
    for (int ch = 0; ch < 8; ++ch) {          // 8 chunks of 32 k per group
        const float* Ab = As + (ch & 1) * 1024;
        const float* Cb = Cs + (ch & 1) * 1024;
        const float* Wb = Ws + (ch & 1) * 32;

        float4 a0, a1, c0, c1, wv;
        const bool pf = (ch + 1 < 8);
        if (pf) {
            const int k0 = (ch + 1) << 5;
            a0 = *(const float4*)(Ag + k0 + lkq * 4);
            a1 = *(const float4*)(Ag + k0 + (lkq + 4) * 4);
            c0 = *(const float4*)(Cg + k0 + lkq * 4);
            c1 = *(const float4*)(Cg + k0 + (lkq + 4) * 4);
            if (t < 8) wv = *(const float4*)(Wg + k0 + t * 4);
        }

#pragma unroll
        for (int kk = 0; kk < 32; kk++) {
            float2 a  = *(const float2*)&Ab[kk * 32 + ty * 2];
            ulonglong2 cv = *(const ulonglong2*)&Cb[kk * 32 + tx * 4];
            const u64 w2  = dup2(Wb[kk]);
            const u64 ad0 = dup2(a.x);
            const u64 ad1 = dup2(a.y);
            step2(acc2[0][0], ad0, cv.x, w2);
            step2(acc2[0][1], ad0, cv.y, w2);
            step2(acc2[1][0], ad1, cv.x, w2);
            step2(acc2[1][1], ad1, cv.y, w2);
        }

        if (pf) {
            float* An = As + ((ch + 1) & 1) * 1024;
            float* Cn = Cs + ((ch + 1) & 1) * 1024;
            An[(lkq*4+0)*32 + lrow] = a0.x; An[(lkq*4+1)*32 + lrow] = a0.y;
            An[(lkq*4+2)*32 + lrow] = a0.z; An[(lkq*4+3)*32 + lrow] = a0.w;
            An[((lkq+4)*4+0)*32 + lrow] = a1.x; An[((lkq+4)*4+1)*32 + lrow] = a1.y;
            An[((lkq+4)*4+2)*32 + lrow] = a1.z; An[((lkq+4)*4+3)*32 + lrow] = a1.w;
            Cn[(lkq*4+0)*32 + lrow] = c0.x; Cn[(lkq*4+1)*32 + lrow] = c0.y;
            Cn[(lkq*4+2)*32 + lrow] = c0.z; Cn[(lkq*4+3)*32 + lrow] = c0.w;
            Cn[((lkq+4)*4+0)*32 + lrow] = c1.x; Cn[((lkq+4)*4+1)*32 + lrow] = c1.y;
            Cn[((lkq+4)*4+2)*32 + lrow] = c1.z; Cn[((lkq+4)*4+3)*32 + lrow] = c1.w;
            if (t < 8) *(float4*)&Ws[((ch + 1) & 1) * 32 + t * 4] = wv;
        }
        __syncthreads();
    }

    // ---- unpack ----
    float acc[2][4];
    unpack2(acc2[0][0], acc[0][0], acc[0][1]);
    unpack2(acc2[0][1], acc[0][2], acc[0][3]);
    unpack2(acc2[1][0], acc[1][0], acc[1][1]);
    unpack2(acc2[1][1], acc[1][2], acc[1][3]);

    // ---- single combine: group1 -> ex, group0 adds ----
    if (g == 1) {
        *(float4*)&ex[t * 8]     = make_float4(acc[0][0], acc[0][1], acc[0][2], acc[0][3]);
        *(float4*)&ex[t * 8 + 4] = make_float4(acc[1][0], acc[1][1], acc[1][2], acc[1][3]);
    }
    __syncthreads();
    if (g == 1) return;
    {
        float4 e0 = *(const float4*)&ex[t * 8];
        float4 e1 = *(const float4*)&ex[t * 8 + 4];
        acc[0][0] += e0.x; acc[0][1] += e0.y; acc[0][2] += e0.z; acc[0][3] += e0.w;
        acc[1][0] += e1.x; acc[1][1] += e1.y; acc[1][2] += e1.z; acc[1][3] += e1.w;
    }

    const float bs2 = *bs2p;
#pragma unroll
    for (int r = 0; r < 2; r++) {
#pragma unroll
        for (int c = 0; c < 4; c++) {
            const int i = i0 + ty * 2 + r;
            const int j = j0 + tx * 4 + c;
            if (i < j) {
                const float s = 1.f / (1.f + __expf(-(acc[r][c] + bs2)));
                out_sim[(size_t)i * BATCH + j] = s;
                out_sim[(size_t)j * BATCH + i] = s;
            } else if (i == j) {
                out_sim[(size_t)i * BATCH + j] = 0.f;
            }
        }
    }
}

// ============================================================
// Launch 3: scores + softmax (reads g_H2), one warp per row.
// ============================================================
__global__ __launch_bounds__(128)
void k_scores(const float* __restrict__ W3, const float* __restrict__ b3,
              float* __restrict__ out_probs, float* __restrict__ out_scores)
{
    const int warp = threadIdx.x >> 5;
    const int lane = threadIdx.x & 31;
    const int row  = blockIdx.x * 4 + warp;
    const float* h = g_H2 + (size_t)row * HID2;

    float acc[PAT];
#pragma unroll
    for (int p = 0; p < PAT; p++) acc[p] = 0.f;

    for (int k = lane; k < HID2; k += 32) {
        const float hv = h[k];
#pragma unroll
        for (int p = 0; p < PAT; p++) acc[p] += hv * W3[p * HID2 + k];
    }
#pragma unroll
    for (int p = 0; p < PAT; p++) {
#pragma unroll
        for (int off = 16; off; off >>= 1)
            acc[p] += __shfl_xor_sync(0xFFFFFFFFu, acc[p], off);
    }
    if (lane == 0) {
        float s[PAT], e[PAT];
        float mx = -1e30f;
#pragma unroll
        for (int p = 0; p < PAT; p++) { s[p] = acc[p] + b3[p]; mx = fmaxf(mx, s[p]); }
        float sum = 0.f;
#pragma unroll
        for (int p = 0; p < PAT; p++) { e[p] = __expf(s[p] - mx); sum += e[p]; }
        const float inv = 1.f / sum;
#pragma unroll
        for (int p = 0; p < PAT; p++) {
            out_scores[row * PAT + p] = s[p];
            out_probs [row * PAT + p] = e[p] * inv;
        }
    }
}

// ============================================================
extern "C" void kernel_launch(void* const* d_in, const int* in_sizes, int n_in,
                              void* d_out, int out_size)
{
    const float* x    = (const float*)d_in[0];
    const float* W1   = (const float*)d_in[1];
    const float* b1   = (const float*)d_in[2];
    const float* gam  = (const float*)d_in[3];
    const float* bet  = (const float*)d_in[4];
    const float* mean = (const float*)d_in[5];
    const float* var  = (const float*)d_in[6];
    const float* W2   = (const float*)d_in[7];
    const float* b2   = (const float*)d_in[8];
    const float* W3   = (const float*)d_in[9];
    const float* b3   = (const float*)d_in[10];
    const float* Wa   = (const float*)d_in[11];
    const float* Wb   = (const float*)d_in[12];
    const float* bs1  = (const float*)d_in[13];
    const float* ws2  = (const float*)d_in[14];
    const float* bs2  = (const float*)d_in[15];

    float* out        = (float*)d_out;
    float* out_probs  = out;
    float* out_scores = out + BATCH * PAT;
    float* out_sim    = out + 2 * BATCH * PAT;

    // 1) H, A, C projections (384 CTAs x 256 threads, split-K2)
    k_proj<<<dim3(16, 8, 3), 256>>>(x, W1, b1, gam, bet, mean, var, Wa, Wb, bs1);
    // 2) sim (136 CTAs, packed f32x2) + H2 (64 CTAs), 256 threads
    k_simh2<<<200, 256>>>(W2, b2, ws2, bs2, out_sim);
    // 3) scores + softmax
    k_scores<<<BATCH / 4, 128>>>(W3, b3, out_probs, out_scores);
}

// round 11
// speedup vs baseline: 1.1020x; 1.0037x over previous
#include <cuda_runtime.h>
#include <math.h>

#define BATCH 512
#define INDIM 256
#define HIDD  512
#define HID2  256
#define PAT   10

typedef unsigned long long u64;

// -------- scratch (no allocations allowed) --------
__device__ __align__(128) float g_H [BATCH * HIDD];
__device__ __align__(128) float g_H2[BATCH * HID2];
__device__ __align__(128) float g_A [BATCH * HIDD];
__device__ __align__(128) float g_C [BATCH * HIDD];

// ---------- packed f32x2 helpers (sm_103a) ----------
__device__ __forceinline__ void unpack2(u64 v, float& lo, float& hi) {
    asm("mov.b64 {%0, %1}, %2;" : "=f"(lo), "=f"(hi) : "l"(v));
}
__device__ __forceinline__ u64 ffma2(u64 a, u64 b, u64 c) {
    u64 d; asm("fma.rn.f32x2 %0, %1, %2, %3;" : "=l"(d) : "l"(a), "l"(b), "l"(c)); return d;
}
// acc += relu(a2 + c2) * w2   (k-packed: both halves are independent k's)
__device__ __forceinline__ void step2(u64& acc, u64 a2, u64 c2, u64 w2) {
    asm("{\n\t"
        ".reg .f32 lo, hi;\n\t"
        ".reg .b64 s;\n\t"
        "add.rn.f32x2 s, %1, %2;\n\t"
        "mov.b64 {lo, hi}, s;\n\t"
        "max.f32 lo, lo, 0f00000000;\n\t"
        "max.f32 hi, hi, 0f00000000;\n\t"
        "mov.b64 s, {lo, hi};\n\t"
        "fma.rn.f32x2 %0, s, %3, %0;\n\t"
        "}"
        : "+l"(acc) : "l"(a2), "l"(c2), "l"(w2));
}

// ============================================================
// k-packed split-K2 GEMM: Out[m][n] = sum_k X[m][k]*W[n][k] (+epi)
// Tile 64m x 32n, 256 thr = 2 K-groups of 128. Row-major smem
// tiles [row][k16] with stride 20 (conflict-free for interleaved
// ownership). Microtile 4m x 4n: m = tym+16q, n = txn+8p.
// Inner 4k-slab: 8 LDS.128 (k-pair operands) + 32 ffma2, no movs.
// Double-buffered, 1 barrier/chunk; single end combine.
// smem: per-group 3840 floats (Xs 2x1280, Wt 2x640), ex 2048.
// mode 0: BN(+b1)+ReLU ; 1: none ; 2: +p0 ; 3: relu(+p0)
// ============================================================
__device__ __forceinline__ void gemm_kp(
    const float* __restrict__ X, const float* __restrict__ W,
    float* __restrict__ Out, int N, int Kstr, int m0, int n0, int mode,
    const float* __restrict__ p0, const float* __restrict__ p1,
    const float* __restrict__ p2, const float* __restrict__ p3,
    const float* __restrict__ p4, float* sm, float* ex)
{
    const int tid = threadIdx.x;
    const int g   = tid >> 7;
    const int t   = tid & 127;

    float* Xs = sm + g * 3840;        // [2][64][20]
    float* Wt = Xs + 2560;            // [2][32][20]

    const int txn = t & 7;            // n = txn + 8p
    const int tym = t >> 3;           // m = tym + 16q

    const int xrow = t & 63;
    const int xkh  = (t >> 6) * 8;    // 0 or 8
    const int wrow = t & 31;
    const int wkq  = (t >> 5) * 4;    // 0,4,8,12

    const int kb = g * (Kstr >> 1);
    const float* Xg = X + (size_t)(m0 + xrow) * Kstr + kb + xkh;
    const float* Wg = W + (size_t)(n0 + wrow) * Kstr + kb + wkq;

    // ---- load chunk 0 ----
    float4 xa = *(const float4*)(Xg);
    float4 xb = *(const float4*)(Xg + 4);
    float4 wv = *(const float4*)(Wg);
    *(float4*)&Xs[xrow * 20 + xkh]     = xa;
    *(float4*)&Xs[xrow * 20 + xkh + 4] = xb;
    *(float4*)&Wt[wrow * 20 + wkq]     = wv;
    __syncthreads();

    u64 acc[4][4];
#pragma unroll
    for (int q = 0; q < 4; q++)
#pragma unroll
        for (int p = 0; p < 4; p++) acc[q][p] = 0ull;

    const int NC = Kstr >> 5;         // chunks of 16 k per group
#pragma unroll 1
    for (int c = 0; c < NC; ++c) {
        const float* Xb = Xs + (c & 1) * 1280;
        const float* Wb = Wt + (c & 1) * 640;

        const bool pf = (c + 1 < NC);
        if (pf) {
            const int ko = (c + 1) << 4;
            xa = *(const float4*)(Xg + ko);
            xb = *(const float4*)(Xg + ko + 4);
            wv = *(const float4*)(Wg + ko);
        }

#pragma unroll
        for (int k4 = 0; k4 < 16; k4 += 4) {
            ulonglong2 a0 = *(const ulonglong2*)&Xb[(tym +  0) * 20 + k4];
            ulonglong2 a1 = *(const ulonglong2*)&Xb[(tym + 16) * 20 + k4];
            ulonglong2 a2 = *(const ulonglong2*)&Xb[(tym + 32) * 20 + k4];
            ulonglong2 a3 = *(const ulonglong2*)&Xb[(tym + 48) * 20 + k4];
            ulonglong2 b0 = *(const ulonglong2*)&Wb[(txn +  0) * 20 + k4];
            ulonglong2 b1 = *(const ulonglong2*)&Wb[(txn +  8) * 20 + k4];
            ulonglong2 b2 = *(const ulonglong2*)&Wb[(txn + 16) * 20 + k4];
            ulonglong2 b3 = *(const ulonglong2*)&Wb[(txn + 24) * 20 + k4];
            acc[0][0] = ffma2(a0.x, b0.x, acc[0][0]); acc[0][0] = ffma2(a0.y, b0.y, acc[0][0]);
            acc[0][1] = ffma2(a0.x, b1.x, acc[0][1]); acc[0][1] = ffma2(a0.y, b1.y, acc[0][1]);
            acc[0][2] = ffma2(a0.x, b2.x, acc[0][2]); acc[0][2] = ffma2(a0.y, b2.y, acc[0][2]);
            acc[0][3] = ffma2(a0.x, b3.x, acc[0][3]); acc[0][3] = ffma2(a0.y, b3.y, acc[0][3]);
            acc[1][0] = ffma2(a1.x, b0.x, acc[1][0]); acc[1][0] = ffma2(a1.y, b0.y, acc[1][0]);
            acc[1][1] = ffma2(a1.x, b1.x, acc[1][1]); acc[1][1] = ffma2(a1.y, b1.y, acc[1][1]);
            acc[1][2] = ffma2(a1.x, b2.x, acc[1][2]); acc[1][2] = ffma2(a1.y, b2.y, acc[1][2]);
            acc[1][3] = ffma2(a1.x, b3.x, acc[1][3]); acc[1][3] = ffma2(a1.y, b3.y, acc[1][3]);
            acc[2][0] = ffma2(a2.x, b0.x, acc[2][0]); acc[2][0] = ffma2(a2.y, b0.y, acc[2][0]);
            acc[2][1] = ffma2(a2.x, b1.x, acc[2][1]); acc[2][1] = ffma2(a2.y, b1.y, acc[2][1]);
            acc[2][2] = ffma2(a2.x, b2.x, acc[2][2]); acc[2][2] = ffma2(a2.y, b2.y, acc[2][2]);
            acc[2][3] = ffma2(a2.x, b3.x, acc[2][3]); acc[2][3] = ffma2(a2.y, b3.y, acc[2][3]);
            acc[3][0] = ffma2(a3.x, b0.x, acc[3][0]); acc[3][0] = ffma2(a3.y, b0.y, acc[3][0]);
            acc[3][1] = ffma2(a3.x, b1.x, acc[3][1]); acc[3][1] = ffma2(a3.y, b1.y, acc[3][1]);
            acc[3][2] = ffma2(a3.x, b2.x, acc[3][2]); acc[3][2] = ffma2(a3.y, b2.y, acc[3][2]);
            acc[3][3] = ffma2(a3.x, b3.x, acc[3][3]); acc[3][3] = ffma2(a3.y, b3.y, acc[3][3]);
        }

        if (pf) {
            float* Xn = Xs + ((c + 1) & 1) * 1280;
            float* Wn = Wt + ((c + 1) & 1) * 640;
            *(float4*)&Xn[xrow * 20 + xkh]     = xa;
            *(float4*)&Xn[xrow * 20 + xkh + 4] = xb;
            *(float4*)&Wn[wrow * 20 + wkq]     = wv;
        }
        __syncthreads();
    }

    // ---- reduce k-pair halves ----
    float va[4][4];
#pragma unroll
    for (int q = 0; q < 4; q++)
#pragma unroll
        for (int p = 0; p < 4; p++) {
            float lo, hi; unpack2(acc[q][p], lo, hi);
            va[q][p] = lo + hi;
        }

    // ---- single combine: group1 -> ex, group0 adds ----
    if (g == 1) {
#pragma unroll
        for (int q = 0; q < 4; q++)
#pragma unroll
            for (int p = 0; p < 4; p++)
                ex[(tym + 16 * q) * 32 + txn + 8 * p] = va[q][p];
    }
    __syncthreads();
    if (g == 1) return;

#pragma unroll
    for (int q = 0; q < 4; q++)
#pragma unroll
        for (int p = 0; p < 4; p++)
            va[q][p] += ex[(tym + 16 * q) * 32 + txn + 8 * p];

    // ---- epilogue (scalar; 4 n values per thread) ----
#pragma unroll
    for (int p = 0; p < 4; p++) {
        const int n = n0 + txn + 8 * p;
        float bias = 0.f, scale = 1.f, off = 0.f;
        if (mode == 0) {
            bias = p0[n];
            scale = p1[n] * rsqrtf(p4[n] + 1e-5f);
            off  = p2[n] - p3[n] * scale;
        } else if (mode == 2 || mode == 3) {
            bias = p0[n];
        }
#pragma unroll
        for (int q = 0; q < 4; q++) {
            const int m = m0 + tym + 16 * q;
            float v = va[q][p];
            if (mode == 0)      v = fmaxf(fmaf(v + bias, scale, off), 0.f);
            else if (mode == 2) v = v + bias;
            else if (mode == 3) v = fmaxf(v + bias, 0.f);
            Out[(size_t)m * N + n] = v;
        }
    }
}

// ============================================================
// Launch 1: three x-projections (H via BN+ReLU, A, C+bs1)
// grid (16 n-tiles, 8 m-tiles, 3 weights), 256 threads.
// ============================================================
__global__ __launch_bounds__(256)
void k_proj(const float* __restrict__ x,
            const float* __restrict__ W1, const float* __restrict__ b1,
            const float* __restrict__ gam, const float* __restrict__ bet,
            const float* __restrict__ mean, const float* __restrict__ var,
            const float* __restrict__ Wa, const float* __restrict__ Wb,
            const float* __restrict__ bs1)
{
    __shared__ __align__(16) float sm[9728];   // 2*3840 + 2048 ex
    float* ex = sm + 7680;
    const int m0 = blockIdx.y * 64;
    const int n0 = blockIdx.x * 32;
    const int z  = blockIdx.z;
    if (z == 0)
        gemm_kp(x, W1, g_H, HIDD, INDIM, m0, n0, 0, b1, gam, bet, mean, var, sm, ex);
    else if (z == 1)
        gemm_kp(x, Wa, g_A, HIDD, INDIM, m0, n0, 1,
                nullptr, nullptr, nullptr, nullptr, nullptr, sm, ex);
    else
        gemm_kp(x, Wb, g_C, HIDD, INDIM, m0, n0, 2,
                bs1, nullptr, nullptr, nullptr, nullptr, sm, ex);
}

// ============================================================
// Launch 2: blocks [0,136) = similarity tiles (upper triangle),
//           blocks [136,200) = H2 = relu(H @ W2^T + b2) 64x32 tiles.
// 256 threads. Sim: k-packed, split-K2, tile 32i x 32j,
// microtile 2i x 4j (i = ty+16r, j = tx+8p), chunks of 32 k,
// row-major smem [row][k32] stride 36, double-buffered.
// ============================================================
__global__ __launch_bounds__(256)
void k_simh2(const float* __restrict__ W2, const float* __restrict__ b2,
             const float* __restrict__ ws2, const float* __restrict__ bs2p,
             float* __restrict__ out_sim)
{
    __shared__ __align__(16) float sm[10368];

    if (blockIdx.x >= 136) {
        const int idx = blockIdx.x - 136;          // 0..63
        gemm_kp(g_H, W2, g_H2, HID2, HIDD, (idx >> 3) * 64, (idx & 7) * 32, 3,
                b2, nullptr, nullptr, nullptr, nullptr, sm, sm + 7680);
        return;
    }

    // ---- similarity tile ----
    const int tid = threadIdx.x;
    const int g   = tid >> 7;
    const int t   = tid & 127;

    // group block: per buf 2336 floats (A 1152 | C 1152 | W 32)
    float* GB = sm + g * 4672;
    float* ex = sm + 9344;            // 1024 floats

    // decode upper-triangle tile (bi <= bj)
    int rb = blockIdx.x, bi = 0;
    while (rb >= 16 - bi) { rb -= 16 - bi; ++bi; }
    const int bj = bi + rb;
    const int i0 = bi * 32, j0 = bj * 32;

    const int tx = t & 7;             // j = tx + 8p
    const int ty = t >> 3;            // i = ty + 16r

    const int lrow = t & 31;
    const int lkh  = (t >> 5) * 8;    // 0,8,16,24
    const int kb   = g * 256;

    const float* Ag = g_A + (size_t)(i0 + lrow) * HIDD + kb + lkh;
    const float* Cg = g_C + (size_t)(j0 + lrow) * HIDD + kb + lkh;
    const float* Wg = ws2 + kb;

    // ---- load chunk 0 ----
    float4 a0 = *(const float4*)(Ag);
    float4 a1 = *(const float4*)(Ag + 4);
    float4 c0 = *(const float4*)(Cg);
    float4 c1 = *(const float4*)(Cg + 4);
    float4 wv = make_float4(0.f, 0.f, 0.f, 0.f);
    if (t < 8) wv = *(const float4*)(Wg + t * 4);
    {
        float* Ab = GB;          // buf 0
        float* Cb = GB + 1152;
        float* Wb = GB + 2304;
        *(float4*)&Ab[lrow * 36 + lkh]     = a0;
        *(float4*)&Ab[lrow * 36 + lkh + 4] = a1;
        *(float4*)&Cb[lrow * 36 + lkh]     = c0;
        *(float4*)&Cb[lrow * 36 + lkh + 4] = c1;
        if (t < 8) *(float4*)&Wb[t * 4] = wv;
    }
    __syncthreads();

    u64 acc2[2][4];
#pragma unroll
    for (int r = 0; r < 2; r++)
#pragma unroll
        for (int p = 0; p < 4; p++) acc2[r][p] = 0ull;

#pragma unroll 1
    for (int ch = 0; ch < 8; ++ch) {          // 8 chunks of 32 k per group
        const float* Ab = GB + (ch & 1) * 2336;
        const float* Cb = Ab + 1152;
        const float* Wb = Ab + 2304;

        const bool pf = (ch + 1 < 8);
        if (pf) {
            const int ko = (ch + 1) << 5;
            a0 = *(const float4*)(Ag + ko);
            a1 = *(const float4*)(Ag + ko + 4);
            c0 = *(const float4*)(Cg + ko);
            c1 = *(const float4*)(Cg + ko + 4);
            if (t < 8) wv = *(const float4*)(Wg + ko + t * 4);
        }

#pragma unroll
        for (int k4 = 0; k4 < 32; k4 += 4) {
            ulonglong2 w2 = *(const ulonglong2*)&Wb[k4];
            ulonglong2 aa0 = *(const ulonglong2*)&Ab[(ty +  0) * 36 + k4];
            ulonglong2 aa1 = *(const ulonglong2*)&Ab[(ty + 16) * 36 + k4];
            ulonglong2 cc0 = *(const ulonglong2*)&Cb[(tx +  0) * 36 + k4];
            ulonglong2 cc1 = *(const ulonglong2*)&Cb[(tx +  8) * 36 + k4];
            ulonglong2 cc2 = *(const ulonglong2*)&Cb[(tx + 16) * 36 + k4];
            ulonglong2 cc3 = *(const ulonglong2*)&Cb[(tx + 24) * 36 + k4];
            step2(acc2[0][0], aa0.x, cc0.x, w2.x); step2(acc2[0][0], aa0.y, cc0.y, w2.y);
            step2(acc2[0][1], aa0.x, cc1.x, w2.x); step2(acc2[0][1], aa0.y, cc1.y, w2.y);
            step2(acc2[0][2], aa0.x, cc2.x, w2.x); step2(acc2[0][2], aa0.y, cc2.y, w2.y);
            step2(acc2[0][3], aa0.x, cc3.x, w2.x); step2(acc2[0][3], aa0.y, cc3.y, w2.y);
            step2(acc2[1][0], aa1.x, cc0.x, w2.x); step2(acc2[1][0], aa1.y, cc0.y, w2.y);
            step2(acc2[1][1], aa1.x, cc1.x, w2.x); step2(acc2[1][1], aa1.y, cc1.y, w2.y);
            step2(acc2[1][2], aa1.x, cc2.x, w2.x); step2(acc2[1][2], aa1.y, cc2.y, w2.y);
            step2(acc2[1][3], aa1.x, cc3.x, w2.x); step2(acc2[1][3], aa1.y, cc3.y, w2.y);
        }

        if (pf) {
            float* An = GB + ((ch + 1) & 1) * 2336;
            float* Cn = An + 1152;
            float* Wn = An + 2304;
            *(float4*)&An[lrow * 36 + lkh]     = a0;
            *(float4*)&An[lrow * 36 + lkh + 4] = a1;
            *(float4*)&Cn[lrow * 36 + lkh]     = c0;
            *(float4*)&Cn[lrow * 36 + lkh + 4] = c1;
            if (t < 8) *(float4*)&Wn[t * 4] = wv;
        }
        __syncthreads();
    }

    // ---- reduce halves ----
    float acc[2][4];
#pragma unroll
    for (int r = 0; r < 2; r++)
#pragma unroll
        for (int p = 0; p < 4; p++) {
            float lo, hi; unpack2(acc2[r][p], lo, hi);
            acc[r][p] = lo + hi;
        }

    // ---- single combine: group1 -> ex, group0 adds ----
    if (g == 1) {
        *(float4*)&ex[t * 8]     = make_float4(acc[0][0], acc[0][1], acc[0][2], acc[0][3]);
        *(float4*)&ex[t * 8 + 4] = make_float4(acc[1][0], acc[1][1], acc[1][2], acc[1][3]);
    }
    __syncthreads();
    if (g == 1) return;
    {
        float4 e0 = *(const float4*)&ex[t * 8];
        float4 e1 = *(const float4*)&ex[t * 8 + 4];
        acc[0][0] += e0.x; acc[0][1] += e0.y; acc[0][2] += e0.z; acc[0][3] += e0.w;
        acc[1][0] += e1.x; acc[1][1] += e1.y; acc[1][2] += e1.z; acc[1][3] += e1.w;
    }

    const float bs2 = *bs2p;
#pragma unroll
    for (int r = 0; r < 2; r++) {
#pragma unroll
        for (int p = 0; p < 4; p++) {
            const int i = i0 + ty + 16 * r;
            const int j = j0 + tx + 8 * p;
            if (i < j) {
                const float s = 1.f / (1.f + __expf(-(acc[r][p] + bs2)));
                out_sim[(size_t)i * BATCH + j] = s;
                out_sim[(size_t)j * BATCH + i] = s;
            } else if (i == j) {
                out_sim[(size_t)i * BATCH + j] = 0.f;
            }
        }
    }
}

// ============================================================
// Launch 3: scores + softmax (reads g_H2), one warp per row.
// ============================================================
__global__ __launch_bounds__(128)
void k_scores(const float* __restrict__ W3, const float* __restrict__ b3,
              float* __restrict__ out_probs, float* __restrict__ out_scores)
{
    const int warp = threadIdx.x >> 5;
    const int lane = threadIdx.x & 31;
    const int row  = blockIdx.x * 4 + warp;
    const float* h = g_H2 + (size_t)row * HID2;

    float acc[PAT];
#pragma unroll
    for (int p = 0; p < PAT; p++) acc[p] = 0.f;

    for (int k = lane; k < HID2; k += 32) {
        const float hv = h[k];
#pragma unroll
        for (int p = 0; p < PAT; p++) acc[p] += hv * W3[p * HID2 + k];
    }
#pragma unroll
    for (int p = 0; p < PAT; p++) {
#pragma unroll
        for (int off = 16; off; off >>= 1)
            acc[p] += __shfl_xor_sync(0xFFFFFFFFu, acc[p], off);
    }
    if (lane == 0) {
        float s[PAT], e[PAT];
        float mx = -1e30f;
#pragma unroll
        for (int p = 0; p < PAT; p++) { s[p] = acc[p] + b3[p]; mx = fmaxf(mx, s[p]); }
        float sum = 0.f;
#pragma unroll
        for (int p = 0; p < PAT; p++) { e[p] = __expf(s[p] - mx); sum += e[p]; }
        const float inv = 1.f / sum;
#pragma unroll
        for (int p = 0; p < PAT; p++) {
            out_scores[row * PAT + p] = s[p];
            out_probs [row * PAT + p] = e[p] * inv;
        }
    }
}

// ============================================================
extern "C" void kernel_launch(void* const* d_in, const int* in_sizes, int n_in,
                              void* d_out, int out_size)
{
    const float* x    = (const float*)d_in[0];
    const float* W1   = (const float*)d_in[1];
    const float* b1   = (const float*)d_in[2];
    const float* gam  = (const float*)d_in[3];
    const float* bet  = (const float*)d_in[4];
    const float* mean = (const float*)d_in[5];
    const float* var  = (const float*)d_in[6];
    const float* W2   = (const float*)d_in[7];
    const float* b2   = (const float*)d_in[8];
    const float* W3   = (const float*)d_in[9];
    const float* b3   = (const float*)d_in[10];
    const float* Wa   = (const float*)d_in[11];
    const float* Wb   = (const float*)d_in[12];
    const float* bs1  = (const float*)d_in[13];
    const float* ws2  = (const float*)d_in[14];
    const float* bs2  = (const float*)d_in[15];

    float* out        = (float*)d_out;
    float* out_probs  = out;
    float* out_scores = out + BATCH * PAT;
    float* out_sim    = out + 2 * BATCH * PAT;

    // 1) H, A, C projections (384 CTAs x 256 threads, k-packed split-K2)
    k_proj<<<dim3(16, 8, 3), 256>>>(x, W1, b1, gam, bet, mean, var, Wa, Wb, bs1);
    // 2) sim (136 CTAs, k-packed) + H2 (64 CTAs), 256 threads
    k_simh2<<<200, 256>>>(W2, b2, ws2, bs2, out_sim);
    // 3) scores + softmax
    k_scores<<<BATCH / 4, 128>>>(W3, b3, out_probs, out_scores);
}

// round 12
// speedup vs baseline: 1.3864x; 1.2581x over previous
#include <cuda_runtime.h>
#include <math.h>
#include <stdint.h>

#define BATCH 512
#define INDIM 256
#define HIDD  512
#define HID2  256
#define PAT   10

typedef unsigned long long u64;

// -------- scratch (no allocations allowed) --------
__device__ __align__(128) float g_H [BATCH * HIDD];
__device__ __align__(128) float g_H2[BATCH * HID2];
__device__ __align__(128) float g_A [BATCH * HIDD];
__device__ __align__(128) float g_C [BATCH * HIDD];

// ---------- helpers ----------
__device__ __forceinline__ void unpack2(u64 v, float& lo, float& hi) {
    asm("mov.b64 {%0, %1}, %2;" : "=f"(lo), "=f"(hi) : "l"(v));
}
__device__ __forceinline__ u64 ffma2(u64 a, u64 b, u64 c) {
    u64 d; asm("fma.rn.f32x2 %0, %1, %2, %3;" : "=l"(d) : "l"(a), "l"(b), "l"(c)); return d;
}
// acc += relu(a2 + c2) * w2   (k-packed halves)
__device__ __forceinline__ void step2(u64& acc, u64 a2, u64 c2, u64 w2) {
    asm("{\n\t"
        ".reg .f32 lo, hi;\n\t"
        ".reg .b64 s;\n\t"
        "add.rn.f32x2 s, %1, %2;\n\t"
        "mov.b64 {lo, hi}, s;\n\t"
        "max.f32 lo, lo, 0f00000000;\n\t"
        "max.f32 hi, hi, 0f00000000;\n\t"
        "mov.b64 s, {lo, hi};\n\t"
        "fma.rn.f32x2 %0, s, %3, %0;\n\t"
        "}"
        : "+l"(acc) : "l"(a2), "l"(c2), "l"(w2));
}
__device__ __forceinline__ uint32_t smem_u32(const void* p) {
    uint32_t a;
    asm("{ .reg .u64 t; cvta.to.shared.u64 t, %1; cvt.u32.u64 %0, t; }" : "=r"(a) : "l"(p));
    return a;
}
#define CP16(dst, src) \
    asm volatile("cp.async.cg.shared.global [%0], [%1], 16;" :: "r"(dst), "l"(src) : "memory")
#define CPCOMMIT() asm volatile("cp.async.commit_group;" ::: "memory")
#define CPWAIT1()  asm volatile("cp.async.wait_group 1;" ::: "memory")

// ============================================================
// cp.async 3-stage GEMM: Out[m][n] = sum_k X[m][k]*W[n][k] (+epi)
// Tile 64m x 32n, 128 threads, K chunks of 16.
// smem stage (1920 floats): X [64][20] at 0, W [32][20] at 1280.
// Microtile 4m x 4n (m = tym+16q, n = txn+8p), k-packed ffma2.
// Loop: wait_group(1) -> sync -> issue(c+2) -> compute(c).
// mode 0: BN(+b1)+ReLU ; 1: none ; 2: +p0 ; 3: relu(+p0)
// ============================================================
__device__ __forceinline__ void gemm_cp(
    const float* __restrict__ X, const float* __restrict__ W,
    float* __restrict__ Out, int N, int K, int m0, int n0, int mode,
    const float* __restrict__ p0, const float* __restrict__ p1,
    const float* __restrict__ p2, const float* __restrict__ p3,
    const float* __restrict__ p4, float* sm)
{
    const int t   = threadIdx.x;
    const int txn = t & 7;
    const int tym = t >> 3;
    const int NC  = K >> 4;

    // per-thread copy pieces (3 x 16B per chunk)
    const float* srcb[3];
    uint32_t     dsto[3];
#pragma unroll
    for (int r = 0; r < 3; r++) {
        const int p = t + (r << 7);
        if (p < 256) {             // X: 64 rows x 4 pieces
            const int row = p >> 2, pc = p & 3;
            srcb[r] = X + (size_t)(m0 + row) * K + pc * 4;
            dsto[r] = (uint32_t)(row * 20 + pc * 4) * 4u;
        } else {                   // W: 32 rows x 4 pieces
            const int q = p - 256;
            const int row = q >> 2, pc = q & 3;
            srcb[r] = W + (size_t)(n0 + row) * K + pc * 4;
            dsto[r] = (uint32_t)(1280 + row * 20 + pc * 4) * 4u;
        }
    }
    const uint32_t smb = smem_u32(sm);

#define G_ISSUE(c) do {                                  \
        const uint32_t sb = smb + ((c) % 3) * 7680u;     \
        CP16(sb + dsto[0], srcb[0] + (c) * 16);          \
        CP16(sb + dsto[1], srcb[1] + (c) * 16);          \
        CP16(sb + dsto[2], srcb[2] + (c) * 16);          \
        CPCOMMIT();                                      \
    } while (0)

    G_ISSUE(0);
    G_ISSUE(1);

    u64 acc[4][4];
#pragma unroll
    for (int q = 0; q < 4; q++)
#pragma unroll
        for (int p = 0; p < 4; p++) acc[q][p] = 0ull;

#pragma unroll 1
    for (int c = 0; c < NC; ++c) {
        CPWAIT1();
        __syncthreads();
        if (c + 2 < NC) { G_ISSUE(c + 2); } else { CPCOMMIT(); }

        const float* Xb = sm + (c % 3) * 1920;
        const float* Wb = Xb + 1280;
#pragma unroll
        for (int k4 = 0; k4 < 16; k4 += 4) {
            ulonglong2 a0 = *(const ulonglong2*)&Xb[(tym +  0) * 20 + k4];
            ulonglong2 a1 = *(const ulonglong2*)&Xb[(tym + 16) * 20 + k4];
            ulonglong2 a2 = *(const ulonglong2*)&Xb[(tym + 32) * 20 + k4];
            ulonglong2 a3 = *(const ulonglong2*)&Xb[(tym + 48) * 20 + k4];
            ulonglong2 b0 = *(const ulonglong2*)&Wb[(txn +  0) * 20 + k4];
            ulonglong2 b1 = *(const ulonglong2*)&Wb[(txn +  8) * 20 + k4];
            ulonglong2 b2 = *(const ulonglong2*)&Wb[(txn + 16) * 20 + k4];
            ulonglong2 b3 = *(const ulonglong2*)&Wb[(txn + 24) * 20 + k4];
            acc[0][0] = ffma2(a0.x, b0.x, acc[0][0]); acc[0][0] = ffma2(a0.y, b0.y, acc[0][0]);
            acc[0][1] = ffma2(a0.x, b1.x, acc[0][1]); acc[0][1] = ffma2(a0.y, b1.y, acc[0][1]);
            acc[0][2] = ffma2(a0.x, b2.x, acc[0][2]); acc[0][2] = ffma2(a0.y, b2.y, acc[0][2]);
            acc[0][3] = ffma2(a0.x, b3.x, acc[0][3]); acc[0][3] = ffma2(a0.y, b3.y, acc[0][3]);
            acc[1][0] = ffma2(a1.x, b0.x, acc[1][0]); acc[1][0] = ffma2(a1.y, b0.y, acc[1][0]);
            acc[1][1] = ffma2(a1.x, b1.x, acc[1][1]); acc[1][1] = ffma2(a1.y, b1.y, acc[1][1]);
            acc[1][2] = ffma2(a1.x, b2.x, acc[1][2]); acc[1][2] = ffma2(a1.y, b2.y, acc[1][2]);
            acc[1][3] = ffma2(a1.x, b3.x, acc[1][3]); acc[1][3] = ffma2(a1.y, b3.y, acc[1][3]);
            acc[2][0] = ffma2(a2.x, b0.x, acc[2][0]); acc[2][0] = ffma2(a2.y, b0.y, acc[2][0]);
            acc[2][1] = ffma2(a2.x, b1.x, acc[2][1]); acc[2][1] = ffma2(a2.y, b1.y, acc[2][1]);
            acc[2][2] = ffma2(a2.x, b2.x, acc[2][2]); acc[2][2] = ffma2(a2.y, b2.y, acc[2][2]);
            acc[2][3] = ffma2(a2.x, b3.x, acc[2][3]); acc[2][3] = ffma2(a2.y, b3.y, acc[2][3]);
            acc[3][0] = ffma2(a3.x, b0.x, acc[3][0]); acc[3][0] = ffma2(a3.y, b0.y, acc[3][0]);
            acc[3][1] = ffma2(a3.x, b1.x, acc[3][1]); acc[3][1] = ffma2(a3.y, b1.y, acc[3][1]);
            acc[3][2] = ffma2(a3.x, b2.x, acc[3][2]); acc[3][2] = ffma2(a3.y, b2.y, acc[3][2]);
            acc[3][3] = ffma2(a3.x, b3.x, acc[3][3]); acc[3][3] = ffma2(a3.y, b3.y, acc[3][3]);
        }
    }
#undef G_ISSUE

    // ---- reduce k-pair halves + epilogue ----
#pragma unroll
    for (int p = 0; p < 4; p++) {
        const int n = n0 + txn + 8 * p;
        float bias = 0.f, scale = 1.f, off = 0.f;
        if (mode == 0) {
            bias  = p0[n];
            scale = p1[n] * rsqrtf(p4[n] + 1e-5f);
            off   = p2[n] - p3[n] * scale;
        } else if (mode == 2 || mode == 3) {
            bias = p0[n];
        }
#pragma unroll
        for (int q = 0; q < 4; q++) {
            float lo, hi; unpack2(acc[q][p], lo, hi);
            float v = lo + hi;
            if (mode == 0)      v = fmaxf(fmaf(v + bias, scale, off), 0.f);
            else if (mode == 2) v = v + bias;
            else if (mode == 3) v = fmaxf(v + bias, 0.f);
            Out[(size_t)(m0 + tym + 16 * q) * N + n] = v;
        }
    }
}

// ============================================================
// Launch 1: three x-projections (H via BN+ReLU, A, C+bs1)
// grid (16 n-tiles, 8 m-tiles, 3 weights), 128 threads.
// ============================================================
__global__ __launch_bounds__(128)
void k_proj(const float* __restrict__ x,
            const float* __restrict__ W1, const float* __restrict__ b1,
            const float* __restrict__ gam, const float* __restrict__ bet,
            const float* __restrict__ mean, const float* __restrict__ var,
            const float* __restrict__ Wa, const float* __restrict__ Wb,
            const float* __restrict__ bs1)
{
    __shared__ __align__(16) float sm[5760];   // 3 stages x 1920
    const int m0 = blockIdx.y * 64;
    const int n0 = blockIdx.x * 32;
    const int z  = blockIdx.z;
    if (z == 0)
        gemm_cp(x, W1, g_H, HIDD, INDIM, m0, n0, 0, b1, gam, bet, mean, var, sm);
    else if (z == 1)
        gemm_cp(x, Wa, g_A, HIDD, INDIM, m0, n0, 1,
                nullptr, nullptr, nullptr, nullptr, nullptr, sm);
    else
        gemm_cp(x, Wb, g_C, HIDD, INDIM, m0, n0, 2,
                bs1, nullptr, nullptr, nullptr, nullptr, sm);
}

// ============================================================
// Launch 2: blocks [0,136) = similarity 32x32 tiles (upper tri),
//           blocks [136,200) = H2 = relu(H@W2^T+b2), 64x32 tiles.
// 128 threads. Sim: cp.async 3-stage, K=512 in 16 chunks of 32,
// smem stage 2336 floats: A [32][36], C [32][36] at 1152, w at 2304.
// Microtile 2i x 4j (i = ty+16r, j = tx+8p), k-packed step2.
// ============================================================
__global__ __launch_bounds__(128)
void k_simh2(const float* __restrict__ W2, const float* __restrict__ b2,
             const float* __restrict__ ws2, const float* __restrict__ bs2p,
             float* __restrict__ out_sim)
{
    __shared__ __align__(16) float sm[7008];   // 3 stages x 2336 (gemm uses 5760)

    if (blockIdx.x >= 136) {
        const int idx = blockIdx.x - 136;          // 0..63
        gemm_cp(g_H, W2, g_H2, HID2, HIDD, (idx >> 3) * 64, (idx & 7) * 32, 3,
                b2, nullptr, nullptr, nullptr, nullptr, sm);
        return;
    }

    const int t  = threadIdx.x;
    const int tx = t & 7;             // j = tx + 8p
    const int ty = t >> 3;            // i = ty + 16r

    // decode upper-triangle tile (bi <= bj)
    int rb = blockIdx.x, bi = 0;
    while (rb >= 16 - bi) { rb -= 16 - bi; ++bi; }
    const int bj = bi + rb;
    const int i0 = bi * 32, j0 = bj * 32;

    // per-thread copy pieces: 4 x 16B (A/C) + w (threads 0..7)
    const float* srcb[4];
    uint32_t     dsto[4];
#pragma unroll
    for (int r = 0; r < 4; r++) {
        const int p = t + (r << 7);
        if (p < 256) {                 // A: 32 rows x 8 pieces
            const int row = p >> 3, pc = p & 7;
            srcb[r] = g_A + (size_t)(i0 + row) * HIDD + pc * 4;
            dsto[r] = (uint32_t)(row * 36 + pc * 4) * 4u;
        } else {                       // C: 32 rows x 8 pieces
            const int q = p - 256;
            const int row = q >> 3, pc = q & 7;
            srcb[r] = g_C + (size_t)(j0 + row) * HIDD + pc * 4;
            dsto[r] = (uint32_t)(1152 + row * 36 + pc * 4) * 4u;
        }
    }
    const bool wcopy = (t < 8);
    const float* wsrc = ws2 + t * 4;
    const uint32_t smb = smem_u32(sm);

#define S_ISSUE(c) do {                                   \
        const uint32_t sb = smb + ((c) % 3) * 9344u;      \
        CP16(sb + dsto[0], srcb[0] + (c) * 32);           \
        CP16(sb + dsto[1], srcb[1] + (c) * 32);           \
        CP16(sb + dsto[2], srcb[2] + (c) * 32);           \
        CP16(sb + dsto[3], srcb[3] + (c) * 32);           \
        if (wcopy) CP16(sb + (2304u + t * 4u) * 4u, wsrc + (c) * 32); \
        CPCOMMIT();                                       \
    } while (0)

    S_ISSUE(0);
    S_ISSUE(1);

    u64 acc2[2][4];
#pragma unroll
    for (int r = 0; r < 2; r++)
#pragma unroll
        for (int p = 0; p < 4; p++) acc2[r][p] = 0ull;

    const int NC = HIDD / 32;          // 16 chunks
#pragma unroll 1
    for (int c = 0; c < NC; ++c) {
        CPWAIT1();
        __syncthreads();
        if (c + 2 < NC) { S_ISSUE(c + 2); } else { CPCOMMIT(); }

        const float* Ab = sm + (c % 3) * 2336;
        const float* Cb = Ab + 1152;
        const float* Wb = Ab + 2304;
#pragma unroll
        for (int k4 = 0; k4 < 32; k4 += 4) {
            ulonglong2 w2  = *(const ulonglong2*)&Wb[k4];
            ulonglong2 aa0 = *(const ulonglong2*)&Ab[(ty +  0) * 36 + k4];
            ulonglong2 aa1 = *(const ulonglong2*)&Ab[(ty + 16) * 36 + k4];
            ulonglong2 cc0 = *(const ulonglong2*)&Cb[(tx +  0) * 36 + k4];
            ulonglong2 cc1 = *(const ulonglong2*)&Cb[(tx +  8) * 36 + k4];
            ulonglong2 cc2 = *(const ulonglong2*)&Cb[(tx + 16) * 36 + k4];
            ulonglong2 cc3 = *(const ulonglong2*)&Cb[(tx + 24) * 36 + k4];
            step2(acc2[0][0], aa0.x, cc0.x, w2.x); step2(acc2[0][0], aa0.y, cc0.y, w2.y);
            step2(acc2[0][1], aa0.x, cc1.x, w2.x); step2(acc2[0][1], aa0.y, cc1.y, w2.y);
            step2(acc2[0][2], aa0.x, cc2.x, w2.x); step2(acc2[0][2], aa0.y, cc2.y, w2.y);
            step2(acc2[0][3], aa0.x, cc3.x, w2.x); step2(acc2[0][3], aa0.y, cc3.y, w2.y);
            step2(acc2[1][0], aa1.x, cc0.x, w2.x); step2(acc2[1][0], aa1.y, cc0.y, w2.y);
            step2(acc2[1][1], aa1.x, cc1.x, w2.x); step2(acc2[1][1], aa1.y, cc1.y, w2.y);
            step2(acc2[1][2], aa1.x, cc2.x, w2.x); step2(acc2[1][2], aa1.y, cc2.y, w2.y);
            step2(acc2[1][3], aa1.x, cc3.x, w2.x); step2(acc2[1][3], aa1.y, cc3.y, w2.y);
        }
    }
#undef S_ISSUE

    const float bs2 = *bs2p;
#pragma unroll
    for (int r = 0; r < 2; r++) {
#pragma unroll
        for (int p = 0; p < 4; p++) {
            float lo, hi; unpack2(acc2[r][p], lo, hi);
            const float a = lo + hi;
            const int i = i0 + ty + 16 * r;
            const int j = j0 + tx + 8 * p;
            if (i < j) {
                const float s = 1.f / (1.f + __expf(-(a + bs2)));
                out_sim[(size_t)i * BATCH + j] = s;
                out_sim[(size_t)j * BATCH + i] = s;
            } else if (i == j) {
                out_sim[(size_t)i * BATCH + j] = 0.f;
            }
        }
    }
}

// ============================================================
// Launch 3: scores + softmax (reads g_H2), one warp per row.
// ============================================================
__global__ __launch_bounds__(128)
void k_scores(const float* __restrict__ W3, const float* __restrict__ b3,
              float* __restrict__ out_probs, float* __restrict__ out_scores)
{
    const int warp = threadIdx.x >> 5;
    const int lane = threadIdx.x & 31;
    const int row  = blockIdx.x * 4 + warp;
    const float* h = g_H2 + (size_t)row * HID2;

    float acc[PAT];
#pragma unroll
    for (int p = 0; p < PAT; p++) acc[p] = 0.f;

    for (int k = lane; k < HID2; k += 32) {
        const float hv = h[k];
#pragma unroll
        for (int p = 0; p < PAT; p++) acc[p] += hv * W3[p * HID2 + k];
    }
#pragma unroll
    for (int p = 0; p < PAT; p++) {
#pragma unroll
        for (int off = 16; off; off >>= 1)
            acc[p] += __shfl_xor_sync(0xFFFFFFFFu, acc[p], off);
    }
    if (lane == 0) {
        float s[PAT], e[PAT];
        float mx = -1e30f;
#pragma unroll
        for (int p = 0; p < PAT; p++) { s[p] = acc[p] + b3[p]; mx = fmaxf(mx, s[p]); }
        float sum = 0.f;
#pragma unroll
        for (int p = 0; p < PAT; p++) { e[p] = __expf(s[p] - mx); sum += e[p]; }
        const float inv = 1.f / sum;
#pragma unroll
        for (int p = 0; p < PAT; p++) {
            out_scores[row * PAT + p] = s[p];
            out_probs [row * PAT + p] = e[p] * inv;
        }
    }
}

// ============================================================
extern "C" void kernel_launch(void* const* d_in, const int* in_sizes, int n_in,
                              void* d_out, int out_size)
{
    const float* x    = (const float*)d_in[0];
    const float* W1   = (const float*)d_in[1];
    const float* b1   = (const float*)d_in[2];
    const float* gam  = (const float*)d_in[3];
    const float* bet  = (const float*)d_in[4];
    const float* mean = (const float*)d_in[5];
    const float* var  = (const float*)d_in[6];
    const float* W2   = (const float*)d_in[7];
    const float* b2   = (const float*)d_in[8];
    const float* W3   = (const float*)d_in[9];
    const float* b3   = (const float*)d_in[10];
    const float* Wa   = (const float*)d_in[11];
    const float* Wb   = (const float*)d_in[12];
    const float* bs1  = (const float*)d_in[13];
    const float* ws2  = (const float*)d_in[14];
    const float* bs2  = (const float*)d_in[15];

    float* out        = (float*)d_out;
    float* out_probs  = out;
    float* out_scores = out + BATCH * PAT;
    float* out_sim    = out + 2 * BATCH * PAT;

    // 1) H, A, C projections (384 CTAs x 128 thr, cp.async 3-stage)
    k_proj<<<dim3(16, 8, 3), 128>>>(x, W1, b1, gam, bet, mean, var, Wa, Wb, bs1);
    // 2) sim (136 CTAs) + H2 (64 CTAs), cp.async 3-stage
    k_simh2<<<200, 128>>>(W2, b2, ws2, bs2, out_sim);
    // 3) scores + softmax
    k_scores<<<BATCH / 4, 128>>>(W3, b3, out_probs, out_scores);
}